// round 3
// baseline (speedup 1.0000x reference)
#include <cuda_runtime.h>
#include <cstdint>

#define BATCH 16
#define SEQ   2048
#define DIM   128
#define LDT   132   // padded row stride for 128-wide tiles (words)
#define LDTP  68    // padded row stride for 64-wide tiles (words)

// partial softmax stats: [B][32 row-tiles][16 k-tiles][2 planes][64 rows]
__device__ float g_stats[BATCH * 32 * 16 * 2 * 64];

__device__ __forceinline__ uint32_t f2tf(float x) {
    uint32_t u;
    asm("cvt.rna.tf32.f32 %0, %1;" : "=r"(u) : "f"(x));
    return u;
}

__device__ __forceinline__ void mma_tf32(float acc[4], const uint32_t a[4], const uint32_t b[2]) {
    asm volatile(
        "mma.sync.aligned.m16n8k8.row.col.f32.tf32.tf32.f32 "
        "{%0,%1,%2,%3}, {%4,%5,%6,%7}, {%8,%9}, {%0,%1,%2,%3};"
        : "+f"(acc[0]), "+f"(acc[1]), "+f"(acc[2]), "+f"(acc[3])
        : "r"(a[0]), "r"(a[1]), "r"(a[2]), "r"(a[3]), "r"(b[0]), "r"(b[1]));
}

extern __shared__ uint32_t smem_u[];

// ---------------------------------------------------------------------------
// Kernel 1: scaled scores for a 64(q) x 128(k) tile + partial softmax stats.
// grid (16 kt, 32 rt, B), 512 threads, 2 CTA/SM (32 warps/SM).
// Warp tile: 16 rows x 32 cols.  wm = w&3 (4 x 16 rows), wn = w>>2 (4 x 32).
// ---------------------------------------------------------------------------
__global__ __launch_bounds__(512, 2)
void k1_scores(const float* __restrict__ Q, const float* __restrict__ K,
               float* __restrict__ attn)
{
    uint32_t* Qs = smem_u;             // [64][LDT]
    uint32_t* Ks = smem_u + 64 * LDT;  // [128][LDT]
    float* sm_max = (float*)(smem_u + (64 + 128) * LDT);  // [4][64]
    float* sm_sum = sm_max + 4 * 64;                       // [4][64]

    const int tid = threadIdx.x;
    const int kt = blockIdx.x;
    const int rt = blockIdx.y;
    const int b  = blockIdx.z;

    const float* Qg = Q + ((size_t)b * SEQ + (size_t)rt * 64) * DIM;
    const float* Kg = K + ((size_t)b * SEQ + (size_t)kt * 128) * DIM;

#pragma unroll
    for (int i = 0; i < 4; i++) {                 // Q tile: 2048 float4
        int f = tid + 512 * i;
        int row = f >> 5;
        int c4 = (f & 31) * 4;
        float4 q4 = *(const float4*)(Qg + row * DIM + c4);
        uint32_t* pq = &Qs[row * LDT + c4];
        pq[0] = f2tf(q4.x); pq[1] = f2tf(q4.y); pq[2] = f2tf(q4.z); pq[3] = f2tf(q4.w);
    }
#pragma unroll
    for (int i = 0; i < 8; i++) {                 // K tile: 4096 float4
        int f = tid + 512 * i;
        int row = f >> 5;
        int c4 = (f & 31) * 4;
        float4 k4 = *(const float4*)(Kg + row * DIM + c4);
        uint32_t* pk = &Ks[row * LDT + c4];
        pk[0] = f2tf(k4.x); pk[1] = f2tf(k4.y); pk[2] = f2tf(k4.z); pk[3] = f2tf(k4.w);
    }
    __syncthreads();

    const int w = tid >> 5, lane = tid & 31;
    const int g = lane >> 2, t = lane & 3;
    const int wm = w & 3;        // 4 blocks x 16 rows
    const int wn = w >> 2;       // 4 blocks x 32 cols

    float acc[4][4];
#pragma unroll
    for (int nt = 0; nt < 4; nt++)
#pragma unroll
        for (int r = 0; r < 4; r++) acc[nt][r] = 0.f;

#pragma unroll
    for (int kk = 0; kk < 16; kk++) {
        const int k0 = kk * 8;
        uint32_t a[4], bf[4][2];
        {
            int r = wm * 16 + g;
            a[0] = Qs[r * LDT + k0 + t];
            a[1] = Qs[(r + 8) * LDT + k0 + t];
            a[2] = Qs[r * LDT + k0 + t + 4];
            a[3] = Qs[(r + 8) * LDT + k0 + t + 4];
        }
#pragma unroll
        for (int nt = 0; nt < 4; nt++) {
            int c = wn * 32 + nt * 8 + g;
            bf[nt][0] = Ks[c * LDT + k0 + t];
            bf[nt][1] = Ks[c * LDT + k0 + t + 4];
        }
#pragma unroll
        for (int nt = 0; nt < 4; nt++)
            mma_tf32(acc[nt], a, bf[nt]);
    }

    const float scale = 0.08838834764831845f;  // 1/sqrt(128)
#pragma unroll
    for (int nt = 0; nt < 4; nt++)
#pragma unroll
        for (int r = 0; r < 4; r++) acc[nt][r] *= scale;

    // ---- per-row max across this warp's 32 cols, combine across 4 wn warps ----
#pragma unroll
    for (int rr = 0; rr < 2; rr++) {
        float mx = -3.4e38f;
#pragma unroll
        for (int nt = 0; nt < 4; nt++)
            mx = fmaxf(mx, fmaxf(acc[nt][2 * rr], acc[nt][2 * rr + 1]));
        mx = fmaxf(mx, __shfl_xor_sync(0xFFFFFFFFu, mx, 1));
        mx = fmaxf(mx, __shfl_xor_sync(0xFFFFFFFFu, mx, 2));
        if (t == 0) sm_max[wn * 64 + wm * 16 + rr * 8 + g] = mx;
    }
    __syncthreads();

#pragma unroll
    for (int rr = 0; rr < 2; rr++) {
        int row = wm * 16 + rr * 8 + g;
        float m = fmaxf(fmaxf(sm_max[row], sm_max[64 + row]),
                        fmaxf(sm_max[128 + row], sm_max[192 + row]));
        float s = 0.f;
#pragma unroll
        for (int nt = 0; nt < 4; nt++)
            s += __expf(acc[nt][2 * rr] - m) + __expf(acc[nt][2 * rr + 1] - m);
        s += __shfl_xor_sync(0xFFFFFFFFu, s, 1);
        s += __shfl_xor_sync(0xFFFFFFFFu, s, 2);
        if (t == 0) sm_sum[wn * 64 + row] = s;
    }
    __syncthreads();

    if (tid < 64) {
        int row = tid;
        float m = fmaxf(fmaxf(sm_max[row], sm_max[64 + row]),
                        fmaxf(sm_max[128 + row], sm_max[192 + row]));
        float l = sm_sum[row] + sm_sum[64 + row] + sm_sum[128 + row] + sm_sum[192 + row];
        size_t base = ((((size_t)b * 32 + rt) * 16 + kt) * 2) * 64;
        g_stats[base + row]      = m;
        g_stats[base + 64 + row] = l;
    }

    // ---- store raw scaled scores ----
    float* Cg = attn + ((size_t)b * SEQ + (size_t)rt * 64) * SEQ + (size_t)kt * 128;
    {
        int r = wm * 16 + g;
#pragma unroll
        for (int nt = 0; nt < 4; nt++) {
            int c = wn * 32 + nt * 8 + 2 * t;
            *(float2*)(Cg + (size_t)r * SEQ + c)       = make_float2(acc[nt][0], acc[nt][1]);
            *(float2*)(Cg + (size_t)(r + 8) * SEQ + c) = make_float2(acc[nt][2], acc[nt][3]);
        }
    }
}

// ---------------------------------------------------------------------------
// Kernel 2: combine stats, normalize scores in place, out = P @ V.
// grid (32 rt, B), 512 threads, 2 CTA/SM.  64-key chunks (32 of them).
// Warp tile over 64x128 out: wm = w&3 (4 x 16 rows), wn = w>>2 (4 x 32 cols).
// ---------------------------------------------------------------------------
__global__ __launch_bounds__(512, 2)
void k2_softmax_pv(const float* __restrict__ V, float* __restrict__ attn,
                   float* __restrict__ out)
{
    uint32_t* Ps = smem_u;              // [64][LDTP]  (64 q rows x 64 keys)
    uint32_t* Vs = smem_u + 64 * LDTP;  // [64][LDT]   (64 k rows x 128 d)
    float* sm_m  = (float*)(smem_u + 64 * LDTP + 64 * LDT);
    float* sm_rl = sm_m + 64;

    const int tid = threadIdx.x;
    const int rt = blockIdx.x;
    const int b  = blockIdx.y;

    float* Arow = attn + ((size_t)b * SEQ + (size_t)rt * 64) * SEQ;

    // ---- Phase A: combine 16 partial (m,l) per row ----
    if (tid < 64) {
        int row = tid;
        size_t base = (((size_t)b * 32 + rt) * 16) * 2 * 64;
        float m = -3.4e38f;
        float mt_v[16], lt_v[16];
#pragma unroll
        for (int kt = 0; kt < 16; kt++) {
            mt_v[kt] = g_stats[base + (size_t)kt * 128 + row];
            lt_v[kt] = g_stats[base + (size_t)kt * 128 + 64 + row];
            m = fmaxf(m, mt_v[kt]);
        }
        float l = 0.f;
#pragma unroll
        for (int kt = 0; kt < 16; kt++)
            l += lt_v[kt] * __expf(mt_v[kt] - m);
        sm_m[row]  = m;
        sm_rl[row] = 1.f / l;
    }
    __syncthreads();

    const int w = tid >> 5, lane = tid & 31;
    const int g = lane >> 2, t = lane & 3;
    const int wm = w & 3;
    const int wn = w >> 2;

    float acc[4][4];
#pragma unroll
    for (int nt = 0; nt < 4; nt++)
#pragma unroll
        for (int r = 0; r < 4; r++) acc[nt][r] = 0.f;

    for (int kc = 0; kc < 32; kc++) {   // 64-key chunks
        // P chunk: read raw scores, normalize, write back fp32, stage tf32.
#pragma unroll
        for (int i = 0; i < 2; i++) {
            int f = tid + 512 * i;         // 1024 float4 (64 rows x 16)
            int row = f >> 4;
            int c4 = (f & 15) * 4;
            float* addr = Arow + (size_t)row * SEQ + kc * 64 + c4;
            float4 s = *(const float4*)addr;
            float m = sm_m[row], rl = sm_rl[row];
            float4 p;
            p.x = __expf(s.x - m) * rl;
            p.y = __expf(s.y - m) * rl;
            p.z = __expf(s.z - m) * rl;
            p.w = __expf(s.w - m) * rl;
            *(float4*)addr = p;
            uint32_t* pp = &Ps[row * LDTP + c4];
            pp[0] = f2tf(p.x); pp[1] = f2tf(p.y); pp[2] = f2tf(p.z); pp[3] = f2tf(p.w);
        }
        // V chunk: 64 rows x 128 d
        const float* Vg = V + ((size_t)b * SEQ + (size_t)kc * 64) * DIM;
#pragma unroll
        for (int i = 0; i < 4; i++) {
            int f = tid + 512 * i;         // 2048 float4
            int row = f >> 5;
            int c4 = (f & 31) * 4;
            float4 v = *(const float4*)(Vg + row * DIM + c4);
            uint32_t* pv = &Vs[row * LDT + c4];
            pv[0] = f2tf(v.x); pv[1] = f2tf(v.y); pv[2] = f2tf(v.z); pv[3] = f2tf(v.w);
        }
        __syncthreads();

#pragma unroll
        for (int kk = 0; kk < 8; kk++) {
            const int k0 = kk * 8;
            uint32_t a[4], bf[4][2];
            {
                int r = wm * 16 + g;
                a[0] = Ps[r * LDTP + k0 + t];
                a[1] = Ps[(r + 8) * LDTP + k0 + t];
                a[2] = Ps[r * LDTP + k0 + t + 4];
                a[3] = Ps[(r + 8) * LDTP + k0 + t + 4];
            }
#pragma unroll
            for (int nt = 0; nt < 4; nt++) {
                int c = wn * 32 + nt * 8 + g;
                bf[nt][0] = Vs[(k0 + t) * LDT + c];
                bf[nt][1] = Vs[(k0 + t + 4) * LDT + c];
            }
#pragma unroll
            for (int nt = 0; nt < 4; nt++)
                mma_tf32(acc[nt], a, bf[nt]);
        }
        __syncthreads();
    }

    float* Og = out + ((size_t)b * SEQ + (size_t)rt * 64) * DIM;
    {
        int r = wm * 16 + g;
#pragma unroll
        for (int nt = 0; nt < 4; nt++) {
            int c = wn * 32 + nt * 8 + 2 * t;
            *(float2*)(Og + (size_t)r * DIM + c)       = make_float2(acc[nt][0], acc[nt][1]);
            *(float2*)(Og + (size_t)(r + 8) * DIM + c) = make_float2(acc[nt][2], acc[nt][3]);
        }
    }
}

// ---------------------------------------------------------------------------
extern "C" void kernel_launch(void* const* d_in, const int* in_sizes, int n_in,
                              void* d_out, int out_size)
{
    const float* Q = (const float*)d_in[0];
    const float* K = (const float*)d_in[1];
    const float* V = (const float*)d_in[2];
    float* out  = (float*)d_out;
    float* attn = out + (size_t)BATCH * SEQ * DIM;

    const int smem1 = (64 + 128) * LDT * 4 + 8 * 64 * 4;
    const int smem2 = 64 * LDTP * 4 + 64 * LDT * 4 + 2 * 64 * 4;

    cudaFuncSetAttribute(k1_scores, cudaFuncAttributeMaxDynamicSharedMemorySize, smem1);
    cudaFuncSetAttribute(k2_softmax_pv, cudaFuncAttributeMaxDynamicSharedMemorySize, smem2);

    dim3 g1(SEQ / 128, SEQ / 64, BATCH);
    k1_scores<<<g1, 512, smem1>>>(Q, K, attn);

    dim3 g2(SEQ / 64, BATCH);
    k2_softmax_pv<<<g2, 512, smem2>>>(V, attn, out);
}

// round 4
// speedup vs baseline: 1.5355x; 1.5355x over previous
#include <cuda_runtime.h>
#include <cuda_fp16.h>
#include <cstdint>
#include <cstring>

#define BATCH 16
#define SEQ   2048
#define DIM   128
#define LP    68     // smem row stride in half2-words (64 data + 4 pad; 68%32==4 -> conflict-free)

// partial softmax stats: [B][16 rt128][16 kt][2 planes][128 rows]
__device__ float g_stats[BATCH * 16 * 16 * 2 * 128];
// e = exp(s - m_tile) as fp16 pairs: [B][S][S/2] half2 words (128 MiB)
__device__ uint32_t e_buf32[(size_t)BATCH * SEQ * (SEQ / 2)];

__device__ __forceinline__ uint32_t packh2(float x, float y) {
    __half2 h = __floats2half2_rn(x, y);
    uint32_t u; memcpy(&u, &h, 4); return u;
}
__device__ __forceinline__ float2 unpackh2(uint32_t u) {
    __half2 h; memcpy(&h, &u, 4); return __half22float2(h);
}

__device__ __forceinline__ void ldsm4(uint32_t& r0, uint32_t& r1, uint32_t& r2, uint32_t& r3,
                                      uint32_t addr) {
    asm volatile("ldmatrix.sync.aligned.m8n8.x4.shared.b16 {%0,%1,%2,%3}, [%4];"
                 : "=r"(r0), "=r"(r1), "=r"(r2), "=r"(r3) : "r"(addr));
}
__device__ __forceinline__ void ldsm4t(uint32_t& r0, uint32_t& r1, uint32_t& r2, uint32_t& r3,
                                       uint32_t addr) {
    asm volatile("ldmatrix.sync.aligned.m8n8.x4.trans.shared.b16 {%0,%1,%2,%3}, [%4];"
                 : "=r"(r0), "=r"(r1), "=r"(r2), "=r"(r3) : "r"(addr));
}
__device__ __forceinline__ void mma_f16(float c[4], const uint32_t a[4], const uint32_t b[2]) {
    asm volatile(
        "mma.sync.aligned.m16n8k16.row.col.f32.f16.f16.f32 "
        "{%0,%1,%2,%3}, {%4,%5,%6,%7}, {%8,%9}, {%0,%1,%2,%3};"
        : "+f"(c[0]), "+f"(c[1]), "+f"(c[2]), "+f"(c[3])
        : "r"(a[0]), "r"(a[1]), "r"(a[2]), "r"(a[3]), "r"(b[0]), "r"(b[1]));
}

extern __shared__ uint32_t smem_u[];

// ---------------------------------------------------------------------------
// Kernel 1: 128(q) x 128(k) score tile -> e = exp(s - m_t) (fp16) + (m_t, l_t).
// grid (16 kt, 16 rt, 16 b), 256 threads, 2 CTA/SM.
// warps: wm = w&1 (2 x 64 rows), wn = w>>1 (4 x 32 cols); acc[4 mt][4 nt][4].
// ---------------------------------------------------------------------------
__global__ __launch_bounds__(256, 2)
void k1_scores(const float* __restrict__ Q, const float* __restrict__ K)
{
    uint32_t* Qs = smem_u;             // [128][LP] half2 words (Q pre-scaled)
    uint32_t* Ks = smem_u + 128 * LP;  // [128][LP] (K rows as B col-major)
    float* smax = (float*)(smem_u + 2 * 128 * LP);  // [4][128]
    float* ssum = smax + 4 * 128;                    // [4][128]

    const int tid = threadIdx.x;
    const int kt = blockIdx.x, rt = blockIdx.y, b = blockIdx.z;
    const float SCALE = 0.08838834764831845f;  // 1/sqrt(128)

    const float* Qg = Q + ((size_t)b * SEQ + (size_t)rt * 128) * DIM;
    const float* Kg = K + ((size_t)b * SEQ + (size_t)kt * 128) * DIM;

#pragma unroll
    for (int i = 0; i < 16; i++) {
        int f = tid + 256 * i;
        int row = f >> 5;
        int c4 = (f & 31) * 4;
        float4 q = *(const float4*)(Qg + row * DIM + c4);
        *(uint2*)(Qs + row * LP + (c4 >> 1)) =
            make_uint2(packh2(q.x * SCALE, q.y * SCALE), packh2(q.z * SCALE, q.w * SCALE));
        float4 k = *(const float4*)(Kg + row * DIM + c4);
        *(uint2*)(Ks + row * LP + (c4 >> 1)) =
            make_uint2(packh2(k.x, k.y), packh2(k.z, k.w));
    }
    __syncthreads();

    const int w = tid >> 5, lane = tid & 31;
    const int g = lane >> 2, t = lane & 3;
    const int wm = w & 1, wn = w >> 1;

    // ldmatrix lane address components
    const int lrow = (lane & 7) + ((lane >> 3) & 1) * 8;  // A rows / B-trans rows
    const int lkp4 = (lane >> 4) * 4;                      // A: k+8 -> +4 words
    const int nB   = (lane & 7) + (lane >> 4) * 8;         // B(non-trans): n row in Ks
    const int kb4  = ((lane >> 3) & 1) * 4;                // B: k+8 -> +4 words

    const uint32_t qbase = (uint32_t)__cvta_generic_to_shared(Qs);
    const uint32_t kbase = (uint32_t)__cvta_generic_to_shared(Ks);
    const uint32_t aw = qbase + (uint32_t)(((wm * 64 + lrow) * LP + lkp4) * 4);
    const uint32_t bw = kbase + (uint32_t)(((wn * 32 + nB) * LP + kb4) * 4);

    float acc[4][4][4];
#pragma unroll
    for (int mt = 0; mt < 4; mt++)
#pragma unroll
        for (int nt = 0; nt < 4; nt++)
#pragma unroll
            for (int r = 0; r < 4; r++) acc[mt][nt][r] = 0.f;

#pragma unroll
    for (int kkk = 0; kkk < 8; kkk++) {
        uint32_t a[4][4], bf[4][2];
#pragma unroll
        for (int mt = 0; mt < 4; mt++)
            ldsm4(a[mt][0], a[mt][1], a[mt][2], a[mt][3],
                  aw + (uint32_t)((mt * 16 * LP + kkk * 8) * 4));
#pragma unroll
        for (int p2 = 0; p2 < 2; p2++) {
            uint32_t r0, r1, r2, r3;
            ldsm4(r0, r1, r2, r3, bw + (uint32_t)((p2 * 16 * LP + kkk * 8) * 4));
            bf[2 * p2][0] = r0; bf[2 * p2][1] = r1;
            bf[2 * p2 + 1][0] = r2; bf[2 * p2 + 1][1] = r3;
        }
#pragma unroll
        for (int mt = 0; mt < 4; mt++)
#pragma unroll
            for (int nt = 0; nt < 4; nt++)
                mma_f16(acc[mt][nt], a[mt], bf[nt]);
    }

    // ---- partial row max ----
#pragma unroll
    for (int mt = 0; mt < 4; mt++) {
        float mx0 = -3.4e38f, mx1 = -3.4e38f;
#pragma unroll
        for (int nt = 0; nt < 4; nt++) {
            mx0 = fmaxf(mx0, fmaxf(acc[mt][nt][0], acc[mt][nt][1]));
            mx1 = fmaxf(mx1, fmaxf(acc[mt][nt][2], acc[mt][nt][3]));
        }
        mx0 = fmaxf(mx0, __shfl_xor_sync(0xFFFFFFFFu, mx0, 1));
        mx0 = fmaxf(mx0, __shfl_xor_sync(0xFFFFFFFFu, mx0, 2));
        mx1 = fmaxf(mx1, __shfl_xor_sync(0xFFFFFFFFu, mx1, 1));
        mx1 = fmaxf(mx1, __shfl_xor_sync(0xFFFFFFFFu, mx1, 2));
        if (t == 0) {
            int r0l = wm * 64 + mt * 16 + g;
            smax[wn * 128 + r0l]     = mx0;
            smax[wn * 128 + r0l + 8] = mx1;
        }
    }
    __syncthreads();

    // ---- e = exp(s - m_t), partial sums, store e fp16 ----
#pragma unroll
    for (int mt = 0; mt < 4; mt++) {
        int r0l = wm * 64 + mt * 16 + g;
        int r1l = r0l + 8;
        float m0 = fmaxf(fmaxf(smax[r0l], smax[128 + r0l]),
                         fmaxf(smax[256 + r0l], smax[384 + r0l]));
        float m1 = fmaxf(fmaxf(smax[r1l], smax[128 + r1l]),
                         fmaxf(smax[256 + r1l], smax[384 + r1l]));
        float s0 = 0.f, s1 = 0.f;
        size_t er0 = ((size_t)b * SEQ + rt * 128 + r0l) * (SEQ / 2);
        size_t er1 = ((size_t)b * SEQ + rt * 128 + r1l) * (SEQ / 2);
#pragma unroll
        for (int nt = 0; nt < 4; nt++) {
            float e00 = __expf(acc[mt][nt][0] - m0);
            float e01 = __expf(acc[mt][nt][1] - m0);
            float e10 = __expf(acc[mt][nt][2] - m1);
            float e11 = __expf(acc[mt][nt][3] - m1);
            s0 += e00 + e01;
            s1 += e10 + e11;
            size_t cp = (size_t)kt * 64 + wn * 16 + nt * 4 + t;
            e_buf32[er0 + cp] = packh2(e00, e01);
            e_buf32[er1 + cp] = packh2(e10, e11);
        }
        s0 += __shfl_xor_sync(0xFFFFFFFFu, s0, 1);
        s0 += __shfl_xor_sync(0xFFFFFFFFu, s0, 2);
        s1 += __shfl_xor_sync(0xFFFFFFFFu, s1, 1);
        s1 += __shfl_xor_sync(0xFFFFFFFFu, s1, 2);
        if (t == 0) {
            ssum[wn * 128 + r0l] = s0;
            ssum[wn * 128 + r1l] = s1;
        }
    }
    __syncthreads();

    if (tid < 128) {
        float m = fmaxf(fmaxf(smax[tid], smax[128 + tid]),
                        fmaxf(smax[256 + tid], smax[384 + tid]));
        float l = ssum[tid] + ssum[128 + tid] + ssum[256 + tid] + ssum[384 + tid];
        size_t base = (((size_t)b * 16 + rt) * 16 + kt) * 256;
        g_stats[base + tid]       = m;
        g_stats[base + 128 + tid] = l;
    }
}

// ---------------------------------------------------------------------------
// Kernel 2: p = e * alpha (write fp32 attn) + out = P @ V.
// grid (32 rt64, 16 b), 256 threads, 2 CTA/SM.
// warps: wm = w&1 (2 x 32 rows), wn = w>>1 (4 x 32 cols); acc[2][4][4].
// ---------------------------------------------------------------------------
__global__ __launch_bounds__(256, 2)
void k2_softmax_pv(const float* __restrict__ V, float* __restrict__ attn,
                   float* __restrict__ out)
{
    uint32_t* Ps = smem_u;             // [64][LP] half2 words of P chunk (128 keys)
    uint32_t* Vs = smem_u + 64 * LP;   // [128][LP] V chunk row-major (128 keys x 128 d)
    float* alpha = (float*)(smem_u + (64 + 128) * LP);  // [16 kt][64 rows]

    const int tid = threadIdx.x;
    const int rt = blockIdx.x;   // 64-row q tile
    const int b  = blockIdx.y;
    const int rt1 = rt >> 1;
    const int roff = (rt & 1) * 64;

    // ---- Phase A: combine stats, alpha[kt][row] = exp(m_t - m) / l ----
    if (tid < 64) {
        int row = tid;
        int grow = roff + row;
        size_t sbase = (((size_t)b * 16 + rt1) * 16) * 256;
        float mv[16], lv[16];
        float m = -3.4e38f;
#pragma unroll
        for (int kt = 0; kt < 16; kt++) {
            mv[kt] = g_stats[sbase + (size_t)kt * 256 + grow];
            lv[kt] = g_stats[sbase + (size_t)kt * 256 + 128 + grow];
            m = fmaxf(m, mv[kt]);
        }
        float l = 0.f;
#pragma unroll
        for (int kt = 0; kt < 16; kt++)
            l += lv[kt] * __expf(mv[kt] - m);
        float rl = 1.f / l;
#pragma unroll
        for (int kt = 0; kt < 16; kt++)
            alpha[kt * 64 + row] = __expf(mv[kt] - m) * rl;
    }
    __syncthreads();

    const int w = tid >> 5, lane = tid & 31;
    const int g = lane >> 2, t = lane & 3;
    const int wm = w & 1, wn = w >> 1;

    const int lrow = (lane & 7) + ((lane >> 3) & 1) * 8;
    const int lkp4 = (lane >> 4) * 4;

    const uint32_t pbase = (uint32_t)__cvta_generic_to_shared(Ps);
    const uint32_t vbase = (uint32_t)__cvta_generic_to_shared(Vs);
    const uint32_t aw = pbase + (uint32_t)(((wm * 32 + lrow) * LP + lkp4) * 4);
    // B trans: rows = key index, col word = wn*16 + p2*8 + (lane>>4)*4
    const uint32_t bw = vbase + (uint32_t)((lrow * LP + wn * 16 + (lane >> 4) * 4) * 4);

    float acc[2][4][4];
#pragma unroll
    for (int mt = 0; mt < 2; mt++)
#pragma unroll
        for (int nt = 0; nt < 4; nt++)
#pragma unroll
            for (int r = 0; r < 4; r++) acc[mt][nt][r] = 0.f;

    const size_t erow = (size_t)b * SEQ + (size_t)rt * 64;

    for (int kc = 0; kc < 16; kc++) {   // 128-key chunks (one k1 tile each)
        // ---- P chunk: p = e * alpha, write fp32 attn, stage fp16 ----
#pragma unroll
        for (int i = 0; i < 8; i++) {
            int idx = tid + 256 * i;        // 2048 quad-groups (64 rows x 32)
            int row = idx >> 5;
            int j   = idx & 31;
            uint2 ee = *(const uint2*)(e_buf32 + (erow + row) * (SEQ / 2) + kc * 64 + j * 2);
            float2 f0 = unpackh2(ee.x);
            float2 f1 = unpackh2(ee.y);
            float a = alpha[kc * 64 + row];
            float4 p = make_float4(f0.x * a, f0.y * a, f1.x * a, f1.y * a);
            *(float4*)(attn + (erow + row) * SEQ + kc * 128 + j * 4) = p;
            *(uint2*)(Ps + row * LP + j * 2) = make_uint2(packh2(p.x, p.y), packh2(p.z, p.w));
        }
        // ---- V chunk: 128 keys x 128 d, row-major half2 ----
        const float* Vg = V + ((size_t)b * SEQ + (size_t)kc * 128) * DIM;
#pragma unroll
        for (int i = 0; i < 16; i++) {
            int f = tid + 256 * i;
            int row = f >> 5;
            int c4 = (f & 31) * 4;
            float4 v = *(const float4*)(Vg + row * DIM + c4);
            *(uint2*)(Vs + row * LP + (c4 >> 1)) =
                make_uint2(packh2(v.x, v.y), packh2(v.z, v.w));
        }
        __syncthreads();

#pragma unroll
        for (int kkk = 0; kkk < 8; kkk++) {
            uint32_t a[2][4], bf[4][2];
#pragma unroll
            for (int mt = 0; mt < 2; mt++)
                ldsm4(a[mt][0], a[mt][1], a[mt][2], a[mt][3],
                      aw + (uint32_t)((mt * 16 * LP + kkk * 8) * 4));
#pragma unroll
            for (int p2 = 0; p2 < 2; p2++) {
                uint32_t r0, r1, r2, r3;
                ldsm4t(r0, r1, r2, r3, bw + (uint32_t)((kkk * 16 * LP + p2 * 8) * 4));
                bf[2 * p2][0] = r0; bf[2 * p2][1] = r1;
                bf[2 * p2 + 1][0] = r2; bf[2 * p2 + 1][1] = r3;
            }
#pragma unroll
            for (int mt = 0; mt < 2; mt++)
#pragma unroll
                for (int nt = 0; nt < 4; nt++)
                    mma_f16(acc[mt][nt], a[mt], bf[nt]);
        }
        __syncthreads();
    }

    // ---- epilogue ----
#pragma unroll
    for (int mt = 0; mt < 2; mt++) {
        int r0 = wm * 32 + mt * 16 + g;
#pragma unroll
        for (int nt = 0; nt < 4; nt++) {
            int c = wn * 32 + nt * 8 + 2 * t;
            float* O0 = out + (erow + r0) * DIM + c;
            float* O1 = out + (erow + r0 + 8) * DIM + c;
            *(float2*)O0 = make_float2(acc[mt][nt][0], acc[mt][nt][1]);
            *(float2*)O1 = make_float2(acc[mt][nt][2], acc[mt][nt][3]);
        }
    }
}

// ---------------------------------------------------------------------------
extern "C" void kernel_launch(void* const* d_in, const int* in_sizes, int n_in,
                              void* d_out, int out_size)
{
    const float* Q = (const float*)d_in[0];
    const float* K = (const float*)d_in[1];
    const float* V = (const float*)d_in[2];
    float* out  = (float*)d_out;
    float* attn = out + (size_t)BATCH * SEQ * DIM;

    const int smem1 = 2 * 128 * LP * 4 + 8 * 128 * 4;           // 73728
    const int smem2 = (64 + 128) * LP * 4 + 16 * 64 * 4;        // 56320

    cudaFuncSetAttribute(k1_scores, cudaFuncAttributeMaxDynamicSharedMemorySize, smem1);
    cudaFuncSetAttribute(k2_softmax_pv, cudaFuncAttributeMaxDynamicSharedMemorySize, smem2);

    dim3 g1(SEQ / 128, SEQ / 128, BATCH);
    k1_scores<<<g1, 256, smem1>>>(Q, K);

    dim3 g2(SEQ / 64, BATCH);
    k2_softmax_pv<<<g2, 256, smem2>>>(V, attn, out);
}

// round 6
// speedup vs baseline: 2.4872x; 1.6198x over previous
#include <cuda_runtime.h>
#include <cuda_fp16.h>
#include <cstdint>
#include <cstring>

#define BATCH 16
#define SEQ   2048
#define DIM   128
#define LP    68     // smem row stride in uint32 (64 data words + 4 pad) -> conflict-free

// fp16 copies of inputs (Q pre-scaled), half2 words, [B][S][D/2]
__device__ uint32_t qh_buf[(size_t)BATCH * SEQ * DIM / 2];
__device__ uint32_t kh_buf[(size_t)BATCH * SEQ * DIM / 2];
__device__ uint32_t vh_buf[(size_t)BATCH * SEQ * DIM / 2];
// e = exp(s - m_tile) fp16: layout [b][kt16][q 2048][64 half2 words]
__device__ uint32_t e_buf32[(size_t)BATCH * 16 * SEQ * 64];
// partial softmax stats: [B][16 rt128][16 kt][m:128 | l:128]
__device__ float g_stats[BATCH * 16 * 16 * 2 * 128];

__device__ __forceinline__ uint32_t packh2(float x, float y) {
    __half2 h = __floats2half2_rn(x, y);
    uint32_t u; memcpy(&u, &h, 4); return u;
}
__device__ __forceinline__ float2 unpackh2(uint32_t u) {
    __half2 h; memcpy(&h, &u, 4); return __half22float2(h);
}

__device__ __forceinline__ void cp_async16(uint32_t dst, const void* src) {
    asm volatile("cp.async.cg.shared.global [%0], [%1], 16;" :: "r"(dst), "l"(src));
}
__device__ __forceinline__ void cp_commit() { asm volatile("cp.async.commit_group;"); }
__device__ __forceinline__ void cp_wait0() { asm volatile("cp.async.wait_group 0;"); }
__device__ __forceinline__ void cp_wait1() { asm volatile("cp.async.wait_group 1;"); }

__device__ __forceinline__ void ldsm4(uint32_t& r0, uint32_t& r1, uint32_t& r2, uint32_t& r3,
                                      uint32_t addr) {
    asm volatile("ldmatrix.sync.aligned.m8n8.x4.shared.b16 {%0,%1,%2,%3}, [%4];"
                 : "=r"(r0), "=r"(r1), "=r"(r2), "=r"(r3) : "r"(addr));
}
__device__ __forceinline__ void ldsm4t(uint32_t& r0, uint32_t& r1, uint32_t& r2, uint32_t& r3,
                                       uint32_t addr) {
    asm volatile("ldmatrix.sync.aligned.m8n8.x4.trans.shared.b16 {%0,%1,%2,%3}, [%4];"
                 : "=r"(r0), "=r"(r1), "=r"(r2), "=r"(r3) : "r"(addr));
}
__device__ __forceinline__ void mma_f16(float c[4], const uint32_t a[4], const uint32_t b[2]) {
    asm volatile(
        "mma.sync.aligned.m16n8k16.row.col.f32.f16.f16.f32 "
        "{%0,%1,%2,%3}, {%4,%5,%6,%7}, {%8,%9}, {%0,%1,%2,%3};"
        : "+f"(c[0]), "+f"(c[1]), "+f"(c[2]), "+f"(c[3])
        : "r"(a[0]), "r"(a[1]), "r"(a[2]), "r"(a[3]), "r"(b[0]), "r"(b[1]));
}

extern __shared__ uint32_t smem_u[];

// ---------------------------------------------------------------------------
// Kernel 0: fp32 -> fp16 conversion (Q pre-scaled by 1/sqrt(D)).
// ---------------------------------------------------------------------------
__global__ __launch_bounds__(256)
void k0_convert(const float* __restrict__ Q, const float* __restrict__ K,
                const float* __restrict__ V)
{
    const float SCALE = 0.08838834764831845f;
    size_t idx = (size_t)blockIdx.x * 256 + threadIdx.x;   // 262144 threads
#pragma unroll
    for (int i = 0; i < 4; i++) {
        size_t f = idx + (size_t)262144 * i;               // float4 id < 1048576
        float4 q = *(const float4*)(Q + f * 4);
        qh_buf[f * 2]     = packh2(q.x * SCALE, q.y * SCALE);
        qh_buf[f * 2 + 1] = packh2(q.z * SCALE, q.w * SCALE);
        float4 k = *(const float4*)(K + f * 4);
        kh_buf[f * 2]     = packh2(k.x, k.y);
        kh_buf[f * 2 + 1] = packh2(k.z, k.w);
        float4 v = *(const float4*)(V + f * 4);
        vh_buf[f * 2]     = packh2(v.x, v.y);
        vh_buf[f * 2 + 1] = packh2(v.z, v.w);
    }
}

// ---------------------------------------------------------------------------
// Kernel 1: 128(q) x 128(k) scores -> e = exp(s - m_t) fp16 + (m_t, l_t).
// grid (16 kt, 16 rt, 16 b), 256 threads, 2 CTA/SM.
// ---------------------------------------------------------------------------
__global__ __launch_bounds__(256, 2)
void k1_scores()
{
    uint32_t* Qs = smem_u;             // [128][LP]  (also reused for e staging)
    uint32_t* Ks = smem_u + 128 * LP;  // [128][LP]
    float* smax = (float*)(smem_u + 2 * 128 * LP);  // [4][128]
    float* ssum = smax + 4 * 128;                    // [4][128]

    const int tid = threadIdx.x;
    const int kt = blockIdx.x, rt = blockIdx.y, b = blockIdx.z;

    const uint32_t* Qg = qh_buf + ((size_t)b * SEQ + (size_t)rt * 128) * 64;
    const uint32_t* Kg = kh_buf + ((size_t)b * SEQ + (size_t)kt * 128) * 64;

    const uint32_t qbase = (uint32_t)__cvta_generic_to_shared(Qs);
    const uint32_t kbase = (uint32_t)__cvta_generic_to_shared(Ks);

#pragma unroll
    for (int i = 0; i < 8; i++) {          // 2048 16B segments each
        int idx = tid + 256 * i;
        int row = idx >> 4;
        int seg = idx & 15;
        cp_async16(qbase + (uint32_t)((row * LP + seg * 4) * 4), Qg + row * 64 + seg * 4);
        cp_async16(kbase + (uint32_t)((row * LP + seg * 4) * 4), Kg + row * 64 + seg * 4);
    }
    cp_commit();
    cp_wait0();
    __syncthreads();

    const int w = tid >> 5, lane = tid & 31;
    const int g = lane >> 2, t = lane & 3;
    const int wm = w & 1, wn = w >> 1;

    const int lrow = (lane & 7) + ((lane >> 3) & 1) * 8;
    const int lkp4 = (lane >> 4) * 4;
    const int nB   = (lane & 7) + (lane >> 4) * 8;
    const int kb4  = ((lane >> 3) & 1) * 4;

    const uint32_t aw = qbase + (uint32_t)(((wm * 64 + lrow) * LP + lkp4) * 4);
    const uint32_t bw = kbase + (uint32_t)(((wn * 32 + nB) * LP + kb4) * 4);

    float acc[4][4][4];
#pragma unroll
    for (int mt = 0; mt < 4; mt++)
#pragma unroll
        for (int nt = 0; nt < 4; nt++)
#pragma unroll
            for (int r = 0; r < 4; r++) acc[mt][nt][r] = 0.f;

#pragma unroll
    for (int kkk = 0; kkk < 8; kkk++) {
        uint32_t a[4][4], bf[4][2];
#pragma unroll
        for (int mt = 0; mt < 4; mt++)
            ldsm4(a[mt][0], a[mt][1], a[mt][2], a[mt][3],
                  aw + (uint32_t)((mt * 16 * LP + kkk * 8) * 4));
#pragma unroll
        for (int p2 = 0; p2 < 2; p2++) {
            uint32_t r0, r1, r2, r3;
            ldsm4(r0, r1, r2, r3, bw + (uint32_t)((p2 * 16 * LP + kkk * 8) * 4));
            bf[2 * p2][0] = r0; bf[2 * p2][1] = r1;
            bf[2 * p2 + 1][0] = r2; bf[2 * p2 + 1][1] = r3;
        }
#pragma unroll
        for (int mt = 0; mt < 4; mt++)
#pragma unroll
            for (int nt = 0; nt < 4; nt++)
                mma_f16(acc[mt][nt], a[mt], bf[nt]);
    }

    // ---- partial row max ----
#pragma unroll
    for (int mt = 0; mt < 4; mt++) {
        float mx0 = -3.4e38f, mx1 = -3.4e38f;
#pragma unroll
        for (int nt = 0; nt < 4; nt++) {
            mx0 = fmaxf(mx0, fmaxf(acc[mt][nt][0], acc[mt][nt][1]));
            mx1 = fmaxf(mx1, fmaxf(acc[mt][nt][2], acc[mt][nt][3]));
        }
        mx0 = fmaxf(mx0, __shfl_xor_sync(0xFFFFFFFFu, mx0, 1));
        mx0 = fmaxf(mx0, __shfl_xor_sync(0xFFFFFFFFu, mx0, 2));
        mx1 = fmaxf(mx1, __shfl_xor_sync(0xFFFFFFFFu, mx1, 1));
        mx1 = fmaxf(mx1, __shfl_xor_sync(0xFFFFFFFFu, mx1, 2));
        if (t == 0) {
            int r0l = wm * 64 + mt * 16 + g;
            smax[wn * 128 + r0l]     = mx0;
            smax[wn * 128 + r0l + 8] = mx1;
        }
    }
    __syncthreads();   // all MMA smem reads done -> Qs reusable

    // ---- e = exp(s - m_t): stage fp16 into Qs, partial sums ----
#pragma unroll
    for (int mt = 0; mt < 4; mt++) {
        int r0l = wm * 64 + mt * 16 + g;
        int r1l = r0l + 8;
        float m0 = fmaxf(fmaxf(smax[r0l], smax[128 + r0l]),
                         fmaxf(smax[256 + r0l], smax[384 + r0l]));
        float m1 = fmaxf(fmaxf(smax[r1l], smax[128 + r1l]),
                         fmaxf(smax[256 + r1l], smax[384 + r1l]));
        float s0 = 0.f, s1 = 0.f;
#pragma unroll
        for (int nt = 0; nt < 4; nt++) {
            float e00 = __expf(acc[mt][nt][0] - m0);
            float e01 = __expf(acc[mt][nt][1] - m0);
            float e10 = __expf(acc[mt][nt][2] - m1);
            float e11 = __expf(acc[mt][nt][3] - m1);
            s0 += e00 + e01;
            s1 += e10 + e11;
            int j = wn * 16 + nt * 4 + t;
            Qs[r0l * LP + j] = packh2(e00, e01);
            Qs[r1l * LP + j] = packh2(e10, e11);
        }
        s0 += __shfl_xor_sync(0xFFFFFFFFu, s0, 1);
        s0 += __shfl_xor_sync(0xFFFFFFFFu, s0, 2);
        s1 += __shfl_xor_sync(0xFFFFFFFFu, s1, 1);
        s1 += __shfl_xor_sync(0xFFFFFFFFu, s1, 2);
        if (t == 0) {
            ssum[wn * 128 + r0l] = s0;
            ssum[wn * 128 + r1l] = s1;
        }
    }
    __syncthreads();

    if (tid < 128) {
        float m = fmaxf(fmaxf(smax[tid], smax[128 + tid]),
                        fmaxf(smax[256 + tid], smax[384 + tid]));
        float l = ssum[tid] + ssum[128 + tid] + ssum[256 + tid] + ssum[384 + tid];
        size_t base = (((size_t)b * 16 + rt) * 16 + kt) * 256;
        g_stats[base + tid]       = m;
        g_stats[base + 128 + tid] = l;
    }

    // ---- coalesced e tile store: contiguous 32 KB block ----
    size_t ebase = (((size_t)(b * 16 + kt)) * SEQ + (size_t)rt * 128) * 64;
#pragma unroll
    for (int i = 0; i < 16; i++) {
        int f = tid + 256 * i;          // 4096 uint2
        int row = f >> 5;
        int c2 = (f & 31) * 2;
        uint2 v = *(uint2*)(Qs + row * LP + c2);
        *(uint2*)(e_buf32 + ebase + (size_t)row * 64 + c2) = v;
    }
}

// ---------------------------------------------------------------------------
// Kernel 2: cp.async double-buffered  out = sum_kt alpha_kt * (E_kt @ V_kt),
// plus attn = e * alpha (fp32).  grid (32 rt64, 16 b), 256 threads, 2 CTA/SM.
// smem: buf{0,1}: E [64][LP] + V [128][LP]; alpha [16][64].
// ---------------------------------------------------------------------------
#define BUFW (64 * LP + 128 * LP)   // 13056 words per buffer
#define ALPHA_OFF (2 * BUFW)        // 26112

__global__ __launch_bounds__(256, 2)
void k2_softmax_pv(float* __restrict__ attn, float* __restrict__ out)
{
    float* alpha_s = (float*)(smem_u + ALPHA_OFF);   // [16][64]

    const int tid = threadIdx.x;
    const int rt = blockIdx.x;   // 64-row q tile
    const int b  = blockIdx.y;
    const int rt1 = rt >> 1;
    const int roff = (rt & 1) * 64;

    const uint32_t sbase = (uint32_t)__cvta_generic_to_shared(smem_u);

    // ---- Phase A: alpha[kt][row] = exp(m_t - m) / l ----
    if (tid < 64) {
        int row = tid;
        int grow = roff + row;
        size_t sb = (((size_t)b * 16 + rt1) * 16) * 256;
        float mv[16], lv[16];
        float m = -3.4e38f;
#pragma unroll
        for (int kt = 0; kt < 16; kt++) {
            mv[kt] = g_stats[sb + (size_t)kt * 256 + grow];
            lv[kt] = g_stats[sb + (size_t)kt * 256 + 128 + grow];
            m = fmaxf(m, mv[kt]);
        }
        float l = 0.f;
#pragma unroll
        for (int kt = 0; kt < 16; kt++)
            l += lv[kt] * __expf(mv[kt] - m);
        float rl = 1.f / l;
#pragma unroll
        for (int kt = 0; kt < 16; kt++)
            alpha_s[kt * 64 + row] = __expf(mv[kt] - m) * rl;
    }

    auto prefetch = [&](int kc, int buf) {
        size_t esrc = (((size_t)(b * 16 + kc)) * SEQ + (size_t)rt * 64) * 64;
#pragma unroll
        for (int i = 0; i < 4; i++) {         // E: 64 rows x 16 segs
            int idx = tid + 256 * i;
            int row = idx >> 4, seg = idx & 15;
            cp_async16(sbase + (uint32_t)((buf * BUFW + row * LP + seg * 4) * 4),
                       e_buf32 + esrc + (size_t)row * 64 + seg * 4);
        }
        const uint32_t* vsrc = vh_buf + ((size_t)b * SEQ + (size_t)kc * 128) * 64;
#pragma unroll
        for (int i = 0; i < 8; i++) {         // V: 128 rows x 16 segs
            int idx = tid + 256 * i;
            int row = idx >> 4, seg = idx & 15;
            cp_async16(sbase + (uint32_t)((buf * BUFW + 64 * LP + row * LP + seg * 4) * 4),
                       vsrc + (size_t)row * 64 + seg * 4);
        }
        cp_commit();
    };

    prefetch(0, 0);
    prefetch(1, 1);
    __syncthreads();   // alpha_s ready

    const int w = tid >> 5, lane = tid & 31;
    const int g = lane >> 2, t = lane & 3;
    const int wm = w & 1, wn = w >> 1;

    const int lrow = (lane & 7) + ((lane >> 3) & 1) * 8;
    const int lkp4 = (lane >> 4) * 4;

    float macc[2][4][4];
#pragma unroll
    for (int mt = 0; mt < 2; mt++)
#pragma unroll
        for (int nt = 0; nt < 4; nt++)
#pragma unroll
            for (int r = 0; r < 4; r++) macc[mt][nt][r] = 0.f;

    const size_t erow = (size_t)b * SEQ + (size_t)rt * 64;

    for (int kc = 0; kc < 16; kc++) {
        const int buf = kc & 1;
        // Drain: for kc<15 the newest pending group is kc+1, so wait_group 1
        // guarantees group kc complete.  At kc==15 the newest pending group IS
        // group 15 itself -> must wait_group 0 (this was the R5 bug).
        if (kc < 15) cp_wait1(); else cp_wait0();
        __syncthreads();

        const uint32_t ebuf = sbase + (uint32_t)(buf * BUFW * 4);
        const uint32_t vbuf = ebuf + (uint32_t)(64 * LP * 4);
        const uint32_t aw = ebuf + (uint32_t)(((wm * 32 + lrow) * LP + lkp4) * 4);
        const uint32_t bw = vbuf + (uint32_t)((lrow * LP + wn * 16 + (lane >> 4) * 4) * 4);

        float cacc[2][4][4];
#pragma unroll
        for (int mt = 0; mt < 2; mt++)
#pragma unroll
            for (int nt = 0; nt < 4; nt++)
#pragma unroll
                for (int r = 0; r < 4; r++) cacc[mt][nt][r] = 0.f;

#pragma unroll
        for (int kkk = 0; kkk < 8; kkk++) {
            uint32_t a[2][4], bf[4][2];
#pragma unroll
            for (int mt = 0; mt < 2; mt++)
                ldsm4(a[mt][0], a[mt][1], a[mt][2], a[mt][3],
                      aw + (uint32_t)((mt * 16 * LP + kkk * 8) * 4));
#pragma unroll
            for (int p2 = 0; p2 < 2; p2++) {
                uint32_t r0, r1, r2, r3;
                ldsm4t(r0, r1, r2, r3, bw + (uint32_t)((kkk * 16 * LP + p2 * 8) * 4));
                bf[2 * p2][0] = r0; bf[2 * p2][1] = r1;
                bf[2 * p2 + 1][0] = r2; bf[2 * p2 + 1][1] = r3;
            }
#pragma unroll
            for (int mt = 0; mt < 2; mt++)
#pragma unroll
                for (int nt = 0; nt < 4; nt++)
                    mma_f16(cacc[mt][nt], a[mt], bf[nt]);
        }

        // ---- attn = e * alpha (fp32, from smem E) ----
        const uint32_t* Eb = smem_u + buf * BUFW;
#pragma unroll
        for (int i = 0; i < 8; i++) {
            int idx = tid + 256 * i;        // 2048 quads (64 rows x 32)
            int row = idx >> 5;
            int j   = idx & 31;
            uint2 ee = *(const uint2*)(Eb + row * LP + j * 2);
            float a = alpha_s[kc * 64 + row];
            float2 f0 = unpackh2(ee.x);
            float2 f1 = unpackh2(ee.y);
            *(float4*)(attn + (erow + row) * SEQ + kc * 128 + j * 4) =
                make_float4(f0.x * a, f0.y * a, f1.x * a, f1.y * a);
        }

        // ---- fold alpha into master accumulator ----
#pragma unroll
        for (int mt = 0; mt < 2; mt++) {
            int r0 = wm * 32 + mt * 16 + g;
            float a0 = alpha_s[kc * 64 + r0];
            float a1 = alpha_s[kc * 64 + r0 + 8];
#pragma unroll
            for (int nt = 0; nt < 4; nt++) {
                macc[mt][nt][0] += a0 * cacc[mt][nt][0];
                macc[mt][nt][1] += a0 * cacc[mt][nt][1];
                macc[mt][nt][2] += a1 * cacc[mt][nt][2];
                macc[mt][nt][3] += a1 * cacc[mt][nt][3];
            }
        }

        __syncthreads();                  // everyone done reading buf
        if (kc + 2 < 16) prefetch(kc + 2, buf);
    }

    // ---- epilogue ----
#pragma unroll
    for (int mt = 0; mt < 2; mt++) {
        int r0 = wm * 32 + mt * 16 + g;
#pragma unroll
        for (int nt = 0; nt < 4; nt++) {
            int c = wn * 32 + nt * 8 + 2 * t;
            *(float2*)(out + (erow + r0) * DIM + c) =
                make_float2(macc[mt][nt][0], macc[mt][nt][1]);
            *(float2*)(out + (erow + r0 + 8) * DIM + c) =
                make_float2(macc[mt][nt][2], macc[mt][nt][3]);
        }
    }
}

// ---------------------------------------------------------------------------
extern "C" void kernel_launch(void* const* d_in, const int* in_sizes, int n_in,
                              void* d_out, int out_size)
{
    const float* Q = (const float*)d_in[0];
    const float* K = (const float*)d_in[1];
    const float* V = (const float*)d_in[2];
    float* out  = (float*)d_out;
    float* attn = out + (size_t)BATCH * SEQ * DIM;

    const int smem1 = 2 * 128 * LP * 4 + 8 * 128 * 4;            // 73728
    const int smem2 = (2 * BUFW + 16 * 64) * 4;                  // 108544

    cudaFuncSetAttribute(k1_scores, cudaFuncAttributeMaxDynamicSharedMemorySize, smem1);
    cudaFuncSetAttribute(k2_softmax_pv, cudaFuncAttributeMaxDynamicSharedMemorySize, smem2);

    k0_convert<<<1024, 256>>>(Q, K, V);

    dim3 g1(SEQ / 128, SEQ / 128, BATCH);
    k1_scores<<<g1, 256, smem1>>>();

    dim3 g2(SEQ / 64, BATCH);
    k2_softmax_pv<<<g2, 256, smem2>>>(attn, out);
}